// round 13
// baseline (speedup 1.0000x reference)
#include <cuda_runtime.h>
#include <cstdint>
#include <cstddef>

// Math collapse (B=1, L=2048, DIM=16, HEADS=DIM_HEAD=1):
// softmax over size-1 axis == 1  =>  out[i, j, d] = v[i]*W_out[d] + b_out[d],
// v[i] = dot(x[i,:], W_qkv[2,:]).  Output (1,2048,2048,16) fp32 = 268 MB.
//
// Round 13: async-proxy store path. Six SM-side store variants all plateau
// at 6.45-6.66 TB/s (LTS fabric cap). This version writes each row's 64B
// pattern into a 16 KB SMEM tile once, then streams the 128 KB row to GMEM
// with 8x cp.async.bulk (TMA bulk store): zero L1tex store wavefronts,
// zero per-sector SM store issue — tests whether L1tex co-limits the cap.

#define L_TOKENS   2048
#define DIM_IN     16
#define ROW_BYTES  (L_TOKENS * DIM_IN * 4)   // 131072 B per i-row
#define TILE_BYTES 16384                     // SMEM tile (16 KB)
#define TILE_F4    (TILE_BYTES / 16)         // 1024 float4 slots
#define COPIES     (ROW_BYTES / TILE_BYTES)  // 8 bulk stores per row
#define THREADS    256

__global__ __launch_bounds__(THREADS, 8)
void attn_broadcast_tma_kernel(const float* __restrict__ x,
                               const float* __restrict__ Wqkv,   // (3,16); v-row at +32
                               const float* __restrict__ Wout,   // (16,1)
                               const float* __restrict__ bout,   // (16,)
                               float* __restrict__ out)
{
    __shared__ __align__(128) float4 tile[TILE_F4];

    const int i   = blockIdx.x;
    const int tid = threadIdx.x;

    // v[i] = dot(x[i, 0:16], Wqkv[2, 0:16]) — L1-broadcast loads, computed
    // redundantly per thread (no reduction needed).
    const float4* xr = (const float4*)(x + i * DIM_IN);
    const float4* wv = (const float4*)(Wqkv + 2 * DIM_IN);
    float v = 0.0f;
    #pragma unroll
    for (int q = 0; q < 4; ++q) {
        float4 a = xr[q], b = wv[q];
        v = fmaf(a.x, b.x, v); v = fmaf(a.y, b.y, v);
        v = fmaf(a.z, b.z, v); v = fmaf(a.w, b.w, v);
    }

    // This thread's float4 lane of the 16-float pattern; (k & 3) == (tid & 3)
    // for all its tile slots since THREADS % 4 == 0.
    const int d_base = (tid & 3) * 4;
    const float4 wo = *(const float4*)(Wout + d_base);
    const float4 bo = *(const float4*)(bout + d_base);
    const float4 val = make_float4(fmaf(v, wo.x, bo.x), fmaf(v, wo.y, bo.y),
                                   fmaf(v, wo.z, bo.z), fmaf(v, wo.w, bo.w));

    // Fill the 16 KB tile with the repeated 64B pattern (4 STS.128/thread).
    #pragma unroll
    for (int k = tid; k < TILE_F4; k += THREADS)
        tile[k] = val;
    __syncthreads();

    // Make generic-proxy SMEM writes visible to the async proxy, then one
    // thread issues 8 bulk stores covering the 128 KB row.
    if (tid == 0) {
        asm volatile("fence.proxy.async.shared::cta;" ::: "memory");

        uint32_t smem_addr;
        asm("{ .reg .u64 t; cvta.to.shared.u64 t, %1; cvt.u32.u64 %0, t; }"
            : "=r"(smem_addr) : "l"(tile));

        char* row = (char*)out + (size_t)i * ROW_BYTES;
        #pragma unroll
        for (int c = 0; c < COPIES; ++c) {
            asm volatile(
                "cp.async.bulk.global.shared::cta.bulk_group [%0], [%1], %2;"
                :: "l"(row + (size_t)c * TILE_BYTES), "r"(smem_addr),
                   "n"(TILE_BYTES)
                : "memory");
        }
        asm volatile("cp.async.bulk.commit_group;" ::: "memory");
        // Wait for completion so SMEM isn't retired while TMA still reads it
        // and all writes are globally visible at grid end.
        asm volatile("cp.async.bulk.wait_group 0;" ::: "memory");
    }
}

extern "C" void kernel_launch(void* const* d_in, const int* in_sizes, int n_in,
                              void* d_out, int out_size)
{
    const float* x    = (const float*)d_in[0];   // (1, 2048, 16)
    const float* Wqkv = (const float*)d_in[1];   // (3, 16)
    const float* Wout = (const float*)d_in[2];   // (16, 1)
    const float* bout = (const float*)d_in[3];   // (16,)
    float* out = (float*)d_out;                  // (1, 2048, 2048, 16) fp32

    attn_broadcast_tma_kernel<<<L_TOKENS, THREADS>>>(x, Wqkv, Wout, bout, out);
}

// round 15
// speedup vs baseline: 1.0478x; 1.0478x over previous
#include <cuda_runtime.h>
#include <cstddef>

// Math collapse (B=1, L=2048, DIM=16, HEADS=DIM_HEAD=1):
// softmax over size-1 axis == 1  =>  out[i, j, d] = v[i]*W_out[d] + b_out[d],
// v[i] = dot(x[i,:], W_qkv[2,:]).  Output (1,2048,2048,16) fp32 = 268 MB.
//
// ROOFLINE KERNEL (converged after 7 structural variants, R2..R13):
// every store path — STG.128/.256, normal/evict-first, SM-side or TMA bulk,
// occ 20%..75%, 1024..2048 CTAs — plateaus at 6.45-6.66 TB/s, matching the
// path-independent LTS chip cap (~6300 B/cyc). 268.4 MB / 6.6 TB/s ~= 40.3us
// kernel time; this variant measures exactly that. Structure: one i-row per
// CTA, 16-float pattern built once in shared, each thread streams one
// register-held float4 lane with perfectly coalesced evict-first stores.

#define L_TOKENS 2048
#define DIM_IN   16
#define ROW_F4   (L_TOKENS * DIM_IN / 4)   // 8192 float4 per i-row
#define THREADS  256

__global__ __launch_bounds__(THREADS, 8)
void attn_broadcast_kernel(const float* __restrict__ x,
                           const float* __restrict__ Wqkv,   // (3,16) row-major; v-row at +32
                           const float* __restrict__ Wout,   // (16,1)
                           const float* __restrict__ bout,   // (16,)
                           float4* __restrict__ out)
{
    const int i   = blockIdx.x;
    const int tid = threadIdx.x;

    __shared__ float4 pat[4];   // the 16-float output pattern for this i

    if (tid < 32) {
        // v[i] = dot(x[i, 0:16], Wqkv[2, 0:16])
        float prod = 0.0f;
        if (tid < 16)
            prod = x[i * DIM_IN + tid] * Wqkv[32 + tid];
        // reduce 16 lanes -> lane 0
        #pragma unroll
        for (int off = 8; off > 0; off >>= 1)
            prod += __shfl_down_sync(0xffffffffu, prod, off);
        float v = __shfl_sync(0xffffffffu, prod, 0);
        if (tid < 16)
            reinterpret_cast<float*>(pat)[tid] = v * Wout[tid] + bout[tid];
    }
    __syncthreads();

    // Stream the 16-float pattern across 2048 j positions.
    // THREADS % 4 == 0, so (k & 3) == (tid & 3) for every iteration:
    // each thread re-stores the same float4 register -> no shared reloads.
    const float4 val = pat[tid & 3];
    const size_t base = (size_t)i * ROW_F4;

    #pragma unroll 8
    for (int k = tid; k < ROW_F4; k += THREADS)
        __stcs(out + base + k, val);   // streaming store: no L2 reuse, evict-first
}

extern "C" void kernel_launch(void* const* d_in, const int* in_sizes, int n_in,
                              void* d_out, int out_size)
{
    const float* x    = (const float*)d_in[0];   // (1, 2048, 16)
    const float* Wqkv = (const float*)d_in[1];   // (3, 16)
    const float* Wout = (const float*)d_in[2];   // (16, 1)
    const float* bout = (const float*)d_in[3];   // (16,)
    float4* out = (float4*)d_out;                // (1, 2048, 2048, 16) fp32

    attn_broadcast_kernel<<<L_TOKENS, THREADS>>>(x, Wqkv, Wout, bout, out);
}